// round 17
// baseline (speedup 1.0000x reference)
#include <cuda_runtime.h>
#include <cuda_fp16.h>
#include <cstdint>

// ---------------------------------------------------------------------------
// MeshUpConv: 3x SplineConv (kernel 3x3, degree 2, open spline) on GB300.
//
// R16 -> R17:
//   * B-row permutation: fragment (nt, 2lkp+b) now maps to actual column
//     lkp*20 + 2nt + b  -> each thread owns 20 CONTIGUOUS output columns
//     per row -> epilogue uses coalesced STG.64 (5 per row vs 10 scattered).
//   * A smem double-buffered -> one __syncthreads per tile.
//   * scan3 (98-block) replaced by 1-block bpref scan; scatter adds the
//     block prefix itself. Shorter sort tail on stream 2.
// ---------------------------------------------------------------------------

#define NMAX  50000
#define EMAX  400000
#define CKOUT 288          // K * C_OUT = 9 * 32
#define NCOLS 320          // 288 Y cols + 32 self cols

__device__ __half g_Y[(size_t)NMAX * CKOUT];
__device__ float  g_agg1[(size_t)NMAX * 32];
__device__ float  g_agg2[(size_t)NMAX * 32];

// sort scratch
struct __align__(16) Edge { int src; int dst; float px; float py; };
__device__ int  g_hist[NMAX];
__device__ int  g_off[NMAX];
__device__ int  g_bsum[128];
__device__ Edge g_ed[EMAX];       // sorted packed edges

// ---- helpers --------------------------------------------------------------
__device__ __forceinline__ uint32_t pack_f16(float a, float b) {
    __half2 t = __floats2half2_rn(a, b);
    return *reinterpret_cast<uint32_t*>(&t);
}
__device__ __forceinline__ void mma_f16(float* c,
                                        uint32_t a0, uint32_t a1, uint32_t a2, uint32_t a3,
                                        uint32_t b0, uint32_t b1) {
    asm("mma.sync.aligned.m16n8k16.row.col.f32.f16.f16.f32 "
        "{%0,%1,%2,%3}, {%4,%5,%6,%7}, {%8,%9}, {%0,%1,%2,%3};"
        : "+f"(c[0]), "+f"(c[1]), "+f"(c[2]), "+f"(c[3])
        : "r"(a0), "r"(a1), "r"(a2), "r"(a3), "r"(b0), "r"(b1));
}
__device__ __forceinline__ void ldsm_x4(uint32_t& r0, uint32_t& r1,
                                        uint32_t& r2, uint32_t& r3, uint32_t a) {
    asm volatile("ldmatrix.sync.aligned.m8n8.x4.shared.b16 {%0,%1,%2,%3}, [%4];"
                 : "=r"(r0), "=r"(r1), "=r"(r2), "=r"(r3) : "r"(a));
}
__device__ __forceinline__ void ldsm_x2(uint32_t& r0, uint32_t& r1, uint32_t a) {
    asm volatile("ldmatrix.sync.aligned.m8n8.x2.shared.b16 {%0,%1}, [%2];"
                 : "=r"(r0), "=r"(r1) : "r"(a));
}
__device__ __forceinline__ uint32_t smem_addr(const void* p) {
    return (uint32_t)__cvta_generic_to_shared(p);
}

// Column permutation: smem B row s = wn*80 + 8*nt + cc  (cc = 2*lkp + b)
//   -> actual output column wn*80 + lkp*20 + 2*nt + b.
__device__ __forceinline__ int bcol_of_row(int s) {
    const int wn = s / 80, j = s % 80;
    const int nt = j >> 3, cc = j & 7;
    return wn * 80 + (cc >> 1) * 20 + nt * 2 + (cc & 1);
}

// SMEM layout. Stride 36 words: bank=(4q+r)%32 -> conflict-free fragments.
// A: 2 x (128 rows x 32 kpairs) double-buffered; B: 320 rows x 32 kpairs.
#define ASTR 36
#define ABUF (128 * ASTR * 4)                    // 18432
#define SM_BIAS 0
#define SM_A    128
#define SM_B    (SM_A + 2 * ABUF)                // 36992
#define SMEM_BYTES (SM_B + 320 * ASTR * 4)       // 83072

// ---------------------------------------------------------------------------
// mma.sync GEMM: per 128-node tile, D[128, 320] = A[128,64] @ Bw[64,320].
// 16 warps = 4(M) x 4(N); warp = 32 rows x 80 cols. fp16 in, fp32 accum.
// A: register prefetch + smem double buffer (1 sync/tile).
// ---------------------------------------------------------------------------
template<int CA, int CB, bool RELU_A, int CIN_W>
__global__ __launch_bounds__(512)
void gemm_mma(const float* __restrict__ xa, const float* __restrict__ xb,
              const float* __restrict__ W, const float* __restrict__ root,
              const float* __restrict__ bias,
              __half* __restrict__ Y, float* __restrict__ agg, int n_nodes)
{
    extern __shared__ __align__(16) char smem[];
    uint32_t* Bb = reinterpret_cast<uint32_t*>(smem + SM_B);
    float*    bs = reinterpret_cast<float*>(smem + SM_BIAS);

    const int tid    = threadIdx.x;
    const int wid    = tid >> 5;
    const int lane   = tid & 31;
    const int warp_m = wid >> 2;
    const int warp_n = wid & 3;
    constexpr int KSTEPS = CIN_W / 16;

    // ---- Stage B once per CTA (fp16; permuted rows; k padded to 64).
    for (int idx = tid; idx < NCOLS * 32; idx += 512) {
        const int s  = idx >> 5;
        const int kp = idx & 31;
        const int gc = bcol_of_row(s);
        const int i0 = 2 * kp, i1 = i0 + 1;
        float v0 = 0.0f, v1 = 0.0f;
        if (i0 < CIN_W) {
            if (gc < CKOUT) {
                const int kk = gc >> 5, cc2 = gc & 31;
                v0 = W[(kk * CIN_W + i0) * 32 + cc2];
                v1 = W[(kk * CIN_W + i1) * 32 + cc2];
            } else {
                v0 = root[i0 * 32 + (gc - CKOUT)];
                v1 = root[i1 * 32 + (gc - CKOUT)];
            }
        }
        Bb[s * ASTR + kp] = pack_f16(v0, v1);
    }
    if (tid < 32) bs[tid] = bias[tid];

    const uint32_t aoffw = (uint32_t)(warp_m * 32 + (lane & 15)) * ASTR + (lane >> 4) * 4;
    const uint32_t boffw = (uint32_t)(warp_n * 80 + (lane & 7)) * ASTR + ((lane >> 3) & 1) * 4;
    const uint32_t aBase = smem_addr(smem + SM_A) + 4 * aoffw;
    const uint32_t bB    = smem_addr(Bb) + 4 * boffw;

    const int ntiles = (n_nodes + 127) >> 7;

    // Per-thread A-staging slots: idx = tid + k*512, k = 0..7.
    auto load_tile = [&](int t, float2* pf) {
        const int n0 = t << 7;
        #pragma unroll
        for (int k = 0; k < 8; k++) {
            const int idx = tid + k * 512;
            const int row = idx >> 5;
            const int kp  = idx & 31;
            const int n   = n0 + row;
            const int i0  = 2 * kp;
            float2 v = make_float2(0.0f, 0.0f);
            if (n < n_nodes) {
                if (i0 < CA) {
                    v = *reinterpret_cast<const float2*>(xa + (size_t)n * CA + i0);
                } else if (CB > 0 && i0 < CA + CB) {
                    v = *reinterpret_cast<const float2*>(xb + (size_t)n * CB + (i0 - CA));
                }
            }
            pf[k] = v;
        }
    };

    int t = blockIdx.x;
    float2 pf[8];
    if (t < ntiles) load_tile(t, pf);
    int buf = 0;

    for (bool first = true; t < ntiles; t += gridDim.x, buf ^= 1, first = false) {
        const int n0 = t << 7;
        uint32_t* Aa = reinterpret_cast<uint32_t*>(smem + SM_A + buf * ABUF);

        // ---- STS the prefetched tile into buf (relu fused).
        #pragma unroll
        for (int k = 0; k < 8; k++) {
            const int idx = tid + k * 512;
            const int row = idx >> 5;
            const int kp  = idx & 31;
            float v0 = pf[k].x, v1 = pf[k].y;
            if (RELU_A) {
                const int i0 = 2 * kp;
                if (i0 < CA) { v0 = fmaxf(v0, 0.0f); v1 = fmaxf(v1, 0.0f); }
            }
            Aa[row * ASTR + kp] = pack_f16(v0, v1);
        }
        __syncthreads();   // A[buf] (and B on first iter) visible

        // ---- Prefetch next tile (latency hidden under the MMA loop).
        const int tn = t + gridDim.x;
        if (tn < ntiles) load_tile(tn, pf);

        const uint32_t aA = aBase + buf * ABUF;

        float acc[2][10][4];
        #pragma unroll
        for (int mt = 0; mt < 2; mt++)
            #pragma unroll
            for (int nt = 0; nt < 10; nt++)
                #pragma unroll
                for (int j = 0; j < 4; j++) acc[mt][nt][j] = 0.0f;

        #pragma unroll
        for (int ks = 0; ks < KSTEPS; ks++) {
            const uint32_t ko = 4u * ks * 8;
            uint32_t a_[2][4];
            #pragma unroll
            for (int mt = 0; mt < 2; mt++)
                ldsm_x4(a_[mt][0], a_[mt][1], a_[mt][2], a_[mt][3],
                        aA + 4u * mt * 16 * ASTR + ko);
            #pragma unroll
            for (int nt = 0; nt < 10; nt++) {
                uint32_t b0, b1;
                ldsm_x2(b0, b1, bB + 4u * nt * 8 * ASTR + ko);
                #pragma unroll
                for (int mt = 0; mt < 2; mt++)
                    mma_f16(acc[mt][nt], a_[mt][0], a_[mt][1], a_[mt][2], a_[mt][3], b0, b1);
            }
        }

        // ---- Epilogue: thread owns 20 contiguous cols per row.
        const int q    = lane >> 2;
        const int lkp  = lane & 3;
        const int colb = warp_n * 80 + lkp * 20;
        #pragma unroll
        for (int mt = 0; mt < 2; mt++) {
            #pragma unroll
            for (int rr = 0; rr < 2; rr++) {
                const int row = n0 + warp_m * 32 + mt * 16 + q + rr * 8;
                if (row >= n_nodes) continue;
                float v[20];
                #pragma unroll
                for (int nt = 0; nt < 10; nt++) {
                    v[2 * nt]     = acc[mt][nt][2 * rr];
                    v[2 * nt + 1] = acc[mt][nt][2 * rr + 1];
                }
                if (colb + 20 <= CKOUT) {
                    // 20 halves = 5 x STG.64, 8B-aligned, lane-contiguous.
                    uint2* dst = reinterpret_cast<uint2*>(Y + (size_t)row * CKOUT + colb);
                    #pragma unroll
                    for (int g = 0; g < 5; g++) {
                        uint2 w;
                        w.x = pack_f16(v[4 * g],     v[4 * g + 1]);
                        w.y = pack_f16(v[4 * g + 2], v[4 * g + 3]);
                        dst[g] = w;
                    }
                } else {
                    #pragma unroll
                    for (int c = 0; c < 20; c++) {
                        const int gc = colb + c;
                        if (gc < CKOUT) {
                            Y[(size_t)row * CKOUT + gc] = __float2half_rn(v[c]);
                        } else {
                            agg[(size_t)row * 32 + (gc - CKOUT)] = v[c] + bs[gc - CKOUT];
                        }
                    }
                }
            }
        }
        // No trailing sync: next STS targets the other A buffer.
    }
}

// ---------------------------------------------------------------------------
// Counting sort of edges by src (overlapped with layer-1 GEMM on stream 2).
// ---------------------------------------------------------------------------
__global__ void hist_kernel(const int* __restrict__ ei, int n_edges) {
    const int e = blockIdx.x * blockDim.x + threadIdx.x;
    if (e < n_edges) atomicAdd(&g_hist[ei[e]], 1);
}
__global__ void scan1(int n) {
    __shared__ int s[512];
    const int tid = threadIdx.x;
    const int b   = blockIdx.x * 512 + tid;
    const int v   = (b < n) ? g_hist[b] : 0;
    s[tid] = v;
    __syncthreads();
    #pragma unroll
    for (int off = 1; off < 512; off <<= 1) {
        int t = (tid >= off) ? s[tid - off] : 0;
        __syncthreads();
        s[tid] += t;
        __syncthreads();
    }
    if (b < n) g_off[b] = s[tid] - v;          // block-local exclusive
    if (tid == 511) g_bsum[blockIdx.x] = s[511];
}
// One-block exclusive scan of block sums (replaces the 98-block scan3).
__global__ void bpref(int nb) {
    __shared__ int s[128];
    const int tid = threadIdx.x;
    const int v = (tid < nb) ? g_bsum[tid] : 0;
    s[tid] = v;
    __syncthreads();
    #pragma unroll
    for (int off = 1; off < 128; off <<= 1) {
        int t = (tid >= off) ? s[tid - off] : 0;
        __syncthreads();
        s[tid] += t;
        __syncthreads();
    }
    if (tid < nb) g_bsum[tid] = s[tid] - v;    // exclusive
}
__global__ void scatter_kernel(const int* __restrict__ ei,
                               const float* __restrict__ pseudo, int n_edges) {
    const int e = blockIdx.x * blockDim.x + threadIdx.x;
    if (e >= n_edges) return;
    const int src = ei[e];
    const int dst = ei[n_edges + e];
    const float2 p = reinterpret_cast<const float2*>(pseudo)[e];
    const int pos = atomicAdd(&g_off[src], 1) + g_bsum[src >> 9];
    Edge ed; ed.src = src; ed.dst = dst; ed.px = p.x; ed.py = p.y;
    g_ed[pos] = ed;                    // single STG.128
}

// ---------------------------------------------------------------------------
// Edge kernel (sorted by src): 4 lanes/edge, 8 channels/lane.
// ---------------------------------------------------------------------------
__global__ __launch_bounds__(256)
void edge_kernel(const __half* __restrict__ Y, float* __restrict__ agg,
                 int n_edges, int n_nodes)
{
    const int t   = blockIdx.x * 256 + threadIdx.x;
    const int e   = t >> 2;
    const int sub = t & 3;            // channels [8*sub, 8*sub+8)
    if (e >= n_edges) return;

    const Edge ed = g_ed[e];
    if ((unsigned)ed.src >= (unsigned)n_nodes || (unsigned)ed.dst >= (unsigned)n_nodes) return;

    const float q00 = 0.5f * (1.0f - ed.px) * (1.0f - ed.px);
    const float q01 = -ed.px * ed.px + ed.px + 0.5f;
    const float q02 = 0.5f * ed.px * ed.px;
    const float q10 = 0.5f * (1.0f - ed.py) * (1.0f - ed.py);
    const float q11 = -ed.py * ed.py + ed.py + 0.5f;
    const float q12 = 0.5f * ed.py * ed.py;

    const float bb[9] = { q10*q00, q10*q01, q10*q02,
                          q11*q00, q11*q01, q11*q02,
                          q12*q00, q12*q01, q12*q02 };

    const uint4* y = reinterpret_cast<const uint4*>(Y + (size_t)ed.src * CKOUT + sub * 8);

    float acc[8] = {0,0,0,0,0,0,0,0};
    #pragma unroll
    for (int k = 0; k < 9; k++) {
        const uint4 qv = y[k * 4];
        const float bk = bb[k];
        const float2 f0 = __half22float2(*reinterpret_cast<const __half2*>(&qv.x));
        const float2 f1 = __half22float2(*reinterpret_cast<const __half2*>(&qv.y));
        const float2 f2 = __half22float2(*reinterpret_cast<const __half2*>(&qv.z));
        const float2 f3 = __half22float2(*reinterpret_cast<const __half2*>(&qv.w));
        acc[0] += bk * f0.x; acc[1] += bk * f0.y;
        acc[2] += bk * f1.x; acc[3] += bk * f1.y;
        acc[4] += bk * f2.x; acc[5] += bk * f2.y;
        acc[6] += bk * f3.x; acc[7] += bk * f3.y;
    }

    float* dp = agg + (size_t)ed.dst * 32 + sub * 8;
    asm volatile("red.global.add.v4.f32 [%0], {%1, %2, %3, %4};"
                 :: "l"(dp), "f"(acc[0]), "f"(acc[1]), "f"(acc[2]), "f"(acc[3]) : "memory");
    asm volatile("red.global.add.v4.f32 [%0], {%1, %2, %3, %4};"
                 :: "l"(dp + 4), "f"(acc[4]), "f"(acc[5]), "f"(acc[6]), "f"(acc[7]) : "memory");
}

__global__ void relu_kernel(float* __restrict__ d, int n)
{
    const int i = blockIdx.x * blockDim.x + threadIdx.x;
    if (i < n) d[i] = fmaxf(d[i], 0.0f);
}

// ---------------------------------------------------------------------------
extern "C" void kernel_launch(void* const* d_in, const int* in_sizes, int n_in,
                              void* d_out, int out_size)
{
    const float* x      = (const float*)d_in[0];
    const int*   ei     = (const int*)d_in[1];     // int64 in ref -> int32 in harness
    const float* pseudo = (const float*)d_in[2];
    const float* skip   = (const float*)d_in[3];
    const float* W1     = (const float*)d_in[4];
    const float* root1  = (const float*)d_in[5];
    const float* b1     = (const float*)d_in[6];
    const float* W2     = (const float*)d_in[7];
    const float* root2  = (const float*)d_in[8];
    const float* b2     = (const float*)d_in[9];

    const int N = in_sizes[0] / 64;
    const int E = in_sizes[1] / 2;
    float* out = (float*)d_out;

    __half* Y;
    float *agg1, *agg2;
    int* hist;
    cudaGetSymbolAddress((void**)&Y,    g_Y);
    cudaGetSymbolAddress((void**)&agg1, g_agg1);
    cudaGetSymbolAddress((void**)&agg2, g_agg2);
    cudaGetSymbolAddress((void**)&hist, g_hist);

    cudaFuncSetAttribute(gemm_mma<64, 0,  false, 64>,
                         cudaFuncAttributeMaxDynamicSharedMemorySize, SMEM_BYTES);
    cudaFuncSetAttribute(gemm_mma<32, 32, true,  64>,
                         cudaFuncAttributeMaxDynamicSharedMemorySize, SMEM_BYTES);
    cudaFuncSetAttribute(gemm_mma<32, 0,  true,  32>,
                         cudaFuncAttributeMaxDynamicSharedMemorySize, SMEM_BYTES);

    const int gemm_grid = 148;
    const int edge_grid = (E * 4 + 255) / 256;
    const int NB        = (N + 511) / 512;

    // ---- Fork: sort chain on stream 2, overlapped with layer-1 GEMM.
    cudaStream_t s2;
    cudaStreamCreateWithFlags(&s2, cudaStreamNonBlocking);
    cudaEvent_t evFork, evJoin;
    cudaEventCreateWithFlags(&evFork, cudaEventDisableTiming);
    cudaEventCreateWithFlags(&evJoin, cudaEventDisableTiming);

    cudaEventRecord(evFork, 0);
    cudaStreamWaitEvent(s2, evFork, 0);

    cudaMemsetAsync(hist, 0, (size_t)N * sizeof(int), s2);
    hist_kernel<<<(E + 255) / 256, 256, 0, s2>>>(ei, E);
    scan1<<<NB, 512, 0, s2>>>(N);
    bpref<<<1, 128, 0, s2>>>(NB);
    scatter_kernel<<<(E + 255) / 256, 256, 0, s2>>>(ei, pseudo, E);
    cudaEventRecord(evJoin, s2);

    // Layer 1 GEMM runs concurrently on the main stream.
    gemm_mma<64, 0, false, 64><<<gemm_grid, 512, SMEM_BYTES>>>(x, nullptr, W1, root1, b1, Y, agg1, N);

    cudaStreamWaitEvent(0, evJoin, 0);   // join: edge1 needs sorted edges
    edge_kernel<<<edge_grid, 256>>>(Y, agg1, E, N);

    // Layer 2: concat(relu(agg1), skip)[N,64] -> agg2   (same W1/root1/b1)
    gemm_mma<32, 32, true, 64><<<gemm_grid, 512, SMEM_BYTES>>>(agg1, skip, W1, root1, b1, Y, agg2, N);
    edge_kernel<<<edge_grid, 256>>>(Y, agg2, E, N);

    // Layer 3: relu(agg2)[N,32] -> d_out  (K = 32 -> 2 k-steps)
    gemm_mma<32, 0, true, 32><<<gemm_grid, 512, SMEM_BYTES>>>(agg2, nullptr, W2, root2, b2, Y, out, N);
    edge_kernel<<<edge_grid, 256>>>(Y, out, E, N);

    relu_kernel<<<(N * 32 + 255) / 256, 256>>>(out, N * 32);
}